// round 3
// baseline (speedup 1.0000x reference)
#include <cuda_runtime.h>
#include <cuda_bf16.h>
#include <cstdint>

#define DEPTH_DIM 256
#define BIN_PIX   32
#define CAP       512
#define MAX_BINS  8192           // supports up to 256K pixels

__device__ int   g_binCnt[MAX_BINS];
__device__ uint2 g_binData[MAX_BINS * CAP];   // {pix5<<16 | depth, conf bits}  (~33.5 MB)

__device__ __forceinline__ float ex2_fast(float x) {
    float y;
    asm("ex2.approx.ftz.f32 %0, %1;" : "=f"(y) : "f"(x));
    return y;
}

// ---------------------------------------------------------------------------
// K1: zero per-bin counters (tiny)
// ---------------------------------------------------------------------------
__global__ void zero_counts_kernel(int nbins) {
    int i = blockIdx.x * blockDim.x + threadIdx.x;
    if (i < nbins) g_binCnt[i] = 0;
}

// ---------------------------------------------------------------------------
// K2: scatter points into their bin slab (order-free slot via atomicAdd)
// ---------------------------------------------------------------------------
__global__ void bin_kernel(const int2* __restrict__ pos,
                           const int*  __restrict__ depth,
                           const float* __restrict__ conf,
                           const int*  __restrict__ pW, int npts) {
    int i = blockIdx.x * blockDim.x + threadIdx.x;
    if (i >= npts) return;
    int W = __ldg(pW);
    int2 uv = __ldg(&pos[i]);
    int lin = uv.y * W + uv.x;
    int bin = lin >> 5;
    int slot = atomicAdd(&g_binCnt[bin], 1);
    if (slot < CAP) {
        uint2 v;
        v.x = ((unsigned)(lin & 31) << 16) | (unsigned)__ldg(&depth[i]);
        v.y = __float_as_uint(__ldg(&conf[i]));
        g_binData[bin * CAP + slot] = v;
    }
}

// ---------------------------------------------------------------------------
// K3: fused accumulate + transposed write.
//   Block = bin = 32 consecutive pixels. Warp w owns pixels 4w..4w+3.
//   Lane L owns depths d = L + 32m  ->  smem tile stride 33 is conflict-free
//   for both the column store and the row read.
//   Per point (warp-uniform): g[d] = exp2(na2 * k^2), L2-normalize via
//   butterfly reduce, add into register acc of the matching pixel.
// ---------------------------------------------------------------------------
__global__ void fused_kernel(float* __restrict__ out, int HW) {
    __shared__ float tile[DEPTH_DIM][33];
    __shared__ uint2 pts[CAP];
    __shared__ int   cnt_s;

    int bin  = blockIdx.x;
    int tid  = threadIdx.x;
    int lane = tid & 31;
    int warp = tid >> 5;

    if (tid == 0) cnt_s = min(g_binCnt[bin], CAP);
    __syncthreads();
    int cnt = cnt_s;
    for (int t = tid; t < cnt; t += 256) pts[t] = g_binData[bin * CAP + t];
    __syncthreads();

    // -0.5 * h^2 * log2(e),  h = 6/255
    const float C = -0.5f * (6.0f / 255.0f) * (6.0f / 255.0f) * 1.4426950408889634f;

    float acc[4][8];
#pragma unroll
    for (int a = 0; a < 4; ++a)
#pragma unroll
        for (int m = 0; m < 8; ++m) acc[a][m] = 0.0f;

    for (int t = 0; t < cnt; ++t) {
        uint2 v = pts[t];                      // broadcast read (no conflicts)
        int pix = (int)(v.x >> 16);
        if ((pix >> 2) != warp) continue;      // warp-uniform skip
        int   jj    = pix & 3;
        int   pd    = (int)(v.x & 0xffff);
        float sigma = __uint_as_float(v.y);
        float na2   = C / (sigma * sigma);

        float g[8];
        float s = 0.0f;
#pragma unroll
        for (int m = 0; m < 8; ++m) {
            int d = lane + 32 * m;
            int k = d - pd - (d > pd);         // window index; dup k=0 at d=pd,pd+1
            float kf = (float)k;
            g[m] = ex2_fast(na2 * kf * kf);
            s = fmaf(g[m], g[m], s);
        }
#pragma unroll
        for (int o = 16; o > 0; o >>= 1)
            s += __shfl_xor_sync(0xffffffffu, s, o);
        float inv = rsqrtf(s);                 // s >= 1 (k=0 term), no eps clamp

        if (jj == 0) {
#pragma unroll
            for (int m = 0; m < 8; ++m) acc[0][m] = fmaf(g[m], inv, acc[0][m]);
        } else if (jj == 1) {
#pragma unroll
            for (int m = 0; m < 8; ++m) acc[1][m] = fmaf(g[m], inv, acc[1][m]);
        } else if (jj == 2) {
#pragma unroll
            for (int m = 0; m < 8; ++m) acc[2][m] = fmaf(g[m], inv, acc[2][m]);
        } else {
#pragma unroll
            for (int m = 0; m < 8; ++m) acc[3][m] = fmaf(g[m], inv, acc[3][m]);
        }
    }

    // stage to smem: column j = warp*4+jj, bank = (lane + j) % 32 -> conflict-free
#pragma unroll
    for (int jj = 0; jj < 4; ++jj)
#pragma unroll
        for (int m = 0; m < 8; ++m)
            tile[lane + 32 * m][warp * 4 + jj] = acc[jj][m];
    __syncthreads();

    // coalesced output: each warp writes 32 consecutive pixels per depth row
    int p = bin * BIN_PIX + lane;
    if (p < HW) {
#pragma unroll
        for (int m = 0; m < 32; ++m) {
            int d = warp + m * 8;
            out[(size_t)d * HW + p] = tile[d][lane];
        }
    }
}

// ---------------------------------------------------------------------------
// Launch
// ---------------------------------------------------------------------------
extern "C" void kernel_launch(void* const* d_in, const int* in_sizes, int n_in,
                              void* d_out, int out_size) {
    const int2*  pos   = (const int2*)d_in[0];   // [N,2] int32 (u=x, v=y)
    const int*   depth = (const int*)d_in[1];    // [N,1] int32
    const float* conf  = (const float*)d_in[2];  // [N,1] float32
    const int*   pW    = (const int*)d_in[4];    // feat_w scalar

    int npts  = in_sizes[1];
    int HW    = out_size / DEPTH_DIM;
    int nbins = (HW + BIN_PIX - 1) / BIN_PIX;

    zero_counts_kernel<<<(nbins + 255) / 256, 256>>>(nbins);
    bin_kernel<<<(npts + 255) / 256, 256>>>(pos, depth, conf, pW, npts);
    fused_kernel<<<nbins, 256>>>((float*)d_out, HW);
}